// round 13
// baseline (speedup 1.0000x reference)
#include <cuda_runtime.h>

// x: (B=8, ns=4, D=512, nc=64) fp32
// out: concat(map_hidden, map_mask), each (B, D, 4, 64, 65) fp32.
// For rel in 0..3, base=1<<rel:
//   out[b,d,rel,i,j] = max(x[b,rel,d, i .. i+k-1]) where k=(j-i)/base,
//   valid when i%base==0, (j-i)%base==0, i<j<64. Mask = 1.0 at hits.
//
// Pure store-bound (~545 MB out). Grid = bd x rel (16384 CTAs).
// Three phases per CTA:
//   0) zero-blast the whole rel block (no sync/LDS/math -> stores flow
//      from cycle 0, hiding the load+build prologue),
//   1) build the running-max table,
//   2) rewrite only the hit elements (contiguous per row -> coalesced).
// Rewrites land on L2-resident lines, so DRAM traffic ~= output size.

#define B_DIM 8
#define D_DIM 512
#define NC 64
#define NJ 65
#define REGION (4 * NC * NJ)        // 16640 floats per half per (b,d)
#define RELBLK (NC * NJ)            // 4160 floats per rel block
#define NCHK (RELBLK / 4)           // 1040 float4 chunks per rel block

template<int REL>
__device__ __forceinline__ void prop3d_rel(
    const float* __restrict__ xrow,     // x[b, REL, d, :]
    float* __restrict__ hid,            // out + bd*REGION + REL*RELBLK
    float* __restrict__ msk,            // hid + half_elems
    float* __restrict__ Sp,             // shared, (64>>REL)^2 words
    float* __restrict__ xsh,            // shared, 64 words
    int tid)
{
    constexpr int W = NC >> REL;        // table rows / row width

    // ---- issue the input load early; latency hides under the blast ----
    float xv = 0.0f;
    if (tid < NC) xv = xrow[tid];

    // ---- phase 0: zero-blast both halves (pure stores, no sync) ----
    const float4 z4 = make_float4(0.0f, 0.0f, 0.0f, 0.0f);
    for (int q = tid; q < NCHK; q += 256) {
        *reinterpret_cast<float4*>(hid + (q << 2)) = z4;
        *reinterpret_cast<float4*>(msk + (q << 2)) = z4;
    }

    if (tid < NC) xsh[tid] = xv;
    __syncthreads();

    // ---- phase 1: build running-max rows: i = r<<REL ----
    if (tid < W) {
        int i  = tid << REL;
        int bo = tid * W;
        int emax = (i + W < NC) ? (i + W) : NC;
        float m = xsh[i];
        Sp[bo] = m;
        #pragma unroll 4
        for (int e = i + 1; e < emax; e++) {
            m = fmaxf(m, xsh[e]);
            Sp[bo + (e - i)] = m;
        }
    }
    __syncthreads();

    // ---- phase 2: hit rewrite. Row r (i = r<<REL) has hits at
    // j = i + k*base, k = 1..kmax, value Sp[r*W + k-1]. Hits are
    // consecutive words for REL=0 (coalesced); tiny counts for REL>0. ----
    const int wid  = tid >> 5;
    const int lane = tid & 31;

    for (int r = wid; r < W; r += 8) {
        int i      = r << REL;
        int kmax   = (NC - 1 - i) >> REL;          // hits k = 1..kmax
        int rowoff = i * NJ + i;
        for (int k = lane + 1; k <= kmax; k += 32) {
            float v  = Sp[r * W + k - 1];
            int  off = rowoff + (k << REL);
            hid[off] = v;
            msk[off] = 1.0f;
        }
    }
}

__global__ __launch_bounds__(256, 8)      // cap regs at 32: protect occupancy
void prop3d_kernel(const float* __restrict__ x, float* __restrict__ out,
                   long half_elems) {
    __shared__ float xsh[NC];
    __shared__ float Sp[4096];            // rel0 worst case: 64x64 (16 KB)

    const int bid = blockIdx.x;
    const int bd  = bid >> 2;             // b*512 + d
    const int rel = bid & 3;
    const int b   = bd >> 9;
    const int d   = bd & 511;
    const int tid = threadIdx.x;

    const float* xrow = x + ((((long)(b << 2) + rel) * D_DIM) + d) * NC;
    float* hid = out + (long)bd * REGION + rel * RELBLK;
    float* msk = hid + half_elems;

    switch (rel) {
        case 0:  prop3d_rel<0>(xrow, hid, msk, Sp, xsh, tid); break;
        case 1:  prop3d_rel<1>(xrow, hid, msk, Sp, xsh, tid); break;
        case 2:  prop3d_rel<2>(xrow, hid, msk, Sp, xsh, tid); break;
        default: prop3d_rel<3>(xrow, hid, msk, Sp, xsh, tid); break;
    }
}

extern "C" void kernel_launch(void* const* d_in, const int* in_sizes, int n_in,
                              void* d_out, int out_size) {
    const float* x = (const float*)d_in[0];
    float* out = (float*)d_out;
    long half = (long)out_size / 2;       // map_hidden elements; map_mask follows

    prop3d_kernel<<<B_DIM * D_DIM * 4, 256>>>(x, out, half);
}

// round 14
// speedup vs baseline: 1.1364x; 1.1364x over previous
#include <cuda_runtime.h>

// x: (B=8, ns=4, D=512, nc=64) fp32
// out: concat(map_hidden, map_mask), each (B, D, 4, 64, 65) fp32.
// For rel in 0..3, base=1<<rel:
//   out[b,d,rel,i,j] = max(x[b,rel,d, i .. i+k-1]) where k=(j-i)/base,
//   valid when i%base==0, (j-i)%base==0, i<j<64. Mask = 1.0 at hits.
//
// Pure store-bound (~545 MB out). R12 structure (fused hidden+mask
// float4 stores, templated REL, incremental (i,j), reg-capped) with
// 128-thread CTAs x 32768: 8 resident CTAs/SM instead of 4, so serial
// per-CTA prologues (load + table build + syncs) overlap across twice
// as many independent streams and store pressure stays continuous.

#define B_DIM 8
#define D_DIM 512
#define NC 64
#define NJ 65
#define REGION (4 * NC * NJ)        // 16640 floats per half per (b,d)
#define RELBLK (NC * NJ)            // 4160 floats per rel block
#define NCHK (RELBLK / 4)           // 1040 float4 chunks per rel block
#define NT 128                      // threads per CTA

template<int REL>
__device__ __forceinline__ void prop3d_rel(
    const float* __restrict__ xrow,     // x[b, REL, d, :]
    float* __restrict__ hid,            // out + bd*REGION + REL*RELBLK
    float* __restrict__ msk,            // hid + half_elems
    float* __restrict__ Sp,             // shared, (64>>REL)^2 words
    float* __restrict__ xsh,            // shared, 64 words
    int tid)
{
    constexpr int W  = NC >> REL;       // table rows / row width
    constexpr int BM = (1 << REL) - 1;

    // ---- stage input row ----
    if (tid < NC) xsh[tid] = xrow[tid];
    __syncthreads();

    // ---- build running-max rows: i = r<<REL ----
    if (tid < W) {
        int i  = tid << REL;
        int bo = tid * W;
        int emax = (i + W < NC) ? (i + W) : NC;
        float m = xsh[i];
        Sp[bo] = m;
        #pragma unroll 4
        for (int e = i + 1; e < emax; e++) {
            m = fmaxf(m, xsh[e]);
            Sp[bo + (e - i)] = m;
        }
    }
    __syncthreads();

    // ---- write loop: 1040 float4 chunks, (i,j) tracked incrementally.
    // chunk q: er = 4q, i = er/65, j = er%65. Stride of 128 chunks =
    // 512 elements = +7 rows, +57 cols (+wrap).
    int q = tid;
    int i = (tid << 2) / 65;            // tid < 128 -> er < 512, i < 8
    int j = (tid << 2) - i * 65;

    while (q < NCHK) {
        float4 hv4, mv4;
        float* hp = reinterpret_cast<float*>(&hv4);
        float* mp = reinterpret_cast<float*>(&mv4);

        #pragma unroll
        for (int l = 0; l < 4; l++) {
            int jj = j + l;
            int ii = i;
            if (jj >= NJ) { jj -= NJ; ii += 1; }  // one row wrap max
            int diff = jj - ii;
            bool hit = (diff > 0) & (jj < NC);
            if (REL > 0) hit = hit & (((ii | diff) & BM) == 0);
            float hv = 0.0f, mv = 0.0f;
            if (hit) {
                hv = Sp[(ii >> REL) * W + (diff >> REL) - 1];
                mv = 1.0f;
            }
            hp[l] = hv;
            mp[l] = mv;
        }

        int off = q << 2;
        *reinterpret_cast<float4*>(hid + off) = hv4;
        *reinterpret_cast<float4*>(msk + off) = mv4;

        q += NT;
        i += 7; j += 57;                // +512 elements
        if (j >= NJ) { j -= NJ; i += 1; }
    }
}

__global__ __launch_bounds__(NT, 8)     // cap regs at 32; 8 CTAs/SM target
void prop3d_kernel(const float* __restrict__ x, float* __restrict__ out,
                   long half_elems) {
    __shared__ float xsh[NC];
    __shared__ float Sp[4096];          // rel0 worst case: 64x64 (16 KB)

    const int bid = blockIdx.x;
    const int bd  = bid >> 2;           // b*512 + d
    const int rel = bid & 3;
    const int b   = bd >> 9;
    const int d   = bd & 511;
    const int tid = threadIdx.x;

    const float* xrow = x + ((((long)(b << 2) + rel) * D_DIM) + d) * NC;
    float* hid = out + (long)bd * REGION + rel * RELBLK;
    float* msk = hid + half_elems;

    switch (rel) {
        case 0:  prop3d_rel<0>(xrow, hid, msk, Sp, xsh, tid); break;
        case 1:  prop3d_rel<1>(xrow, hid, msk, Sp, xsh, tid); break;
        case 2:  prop3d_rel<2>(xrow, hid, msk, Sp, xsh, tid); break;
        default: prop3d_rel<3>(xrow, hid, msk, Sp, xsh, tid); break;
    }
}

extern "C" void kernel_launch(void* const* d_in, const int* in_sizes, int n_in,
                              void* d_out, int out_size) {
    const float* x = (const float*)d_in[0];
    float* out = (float*)d_out;
    long half = (long)out_size / 2;     // map_hidden elements; map_mask follows

    prop3d_kernel<<<B_DIM * D_DIM * 4, NT>>>(x, out, half);
}

// round 15
// speedup vs baseline: 1.1512x; 1.0131x over previous
#include <cuda_runtime.h>

// x: (B=8, ns=4, D=512, nc=64) fp32
// out: concat(map_hidden, map_mask), each (B, D, 4, 64, 65) fp32.
// For rel in 0..3, base=1<<rel:
//   out[b,d,rel,i,j] = max(x[b,rel,d, i .. i+k-1]) where k=(j-i)/base,
//   valid when i%base==0, (j-i)%base==0, i<j<64. Mask = 1.0 at hits.
//
// Pure store-bound (~545 MB out). R12 champion shape: grid = bd x rel
// (16384 CTAs x 256 thr), fused hidden+mask float4 stores, templated REL,
// incremental (i,j), reg-capped. This round: write loop software-pipelined
// with TWO independent chunk cursors (A: tid+512s, B: tid+256+512s) so
// control math of one chunk overlaps store issue of the other at ~zero
// register cost (carried state = 6 ints; cap keeps regs <= 32).

#define B_DIM 8
#define D_DIM 512
#define NC 64
#define NJ 65
#define REGION (4 * NC * NJ)        // 16640 floats per half per (b,d)
#define RELBLK (NC * NJ)            // 4160 floats per rel block
#define NCHK (RELBLK / 4)           // 1040 float4 chunks per rel block

template<int REL>
__device__ __forceinline__ void emit_chunk(
    float* __restrict__ hid, float* __restrict__ msk,
    const float* __restrict__ Sp, int q, int i, int j)
{
    constexpr int W  = NC >> REL;
    constexpr int BM = (1 << REL) - 1;

    float4 hv4, mv4;
    float* hp = reinterpret_cast<float*>(&hv4);
    float* mp = reinterpret_cast<float*>(&mv4);

    #pragma unroll
    for (int l = 0; l < 4; l++) {
        int jj = j + l;
        int ii = i;
        if (jj >= NJ) { jj -= NJ; ii += 1; }      // one row wrap max
        int diff = jj - ii;
        bool hit = (diff > 0) & (jj < NC);
        if (REL > 0) hit = hit & (((ii | diff) & BM) == 0);
        float hv = 0.0f, mv = 0.0f;
        if (hit) {
            hv = Sp[(ii >> REL) * W + (diff >> REL) - 1];
            mv = 1.0f;
        }
        hp[l] = hv;
        mp[l] = mv;
    }

    int off = q << 2;
    *reinterpret_cast<float4*>(hid + off) = hv4;
    *reinterpret_cast<float4*>(msk + off) = mv4;
}

template<int REL>
__device__ __forceinline__ void prop3d_rel(
    const float* __restrict__ xrow,     // x[b, REL, d, :]
    float* __restrict__ hid,            // out + bd*REGION + REL*RELBLK
    float* __restrict__ msk,            // hid + half_elems
    float* __restrict__ Sp,             // shared, (64>>REL)^2 words
    float* __restrict__ xsh,            // shared, 64 words
    int tid)
{
    constexpr int W = NC >> REL;        // table rows / row width

    // ---- stage input row ----
    if (tid < NC) xsh[tid] = xrow[tid];
    __syncthreads();

    // ---- build running-max rows: i = r<<REL ----
    if (tid < W) {
        int i  = tid << REL;
        int bo = tid * W;
        int emax = (i + W < NC) ? (i + W) : NC;
        float m = xsh[i];
        Sp[bo] = m;
        #pragma unroll 4
        for (int e = i + 1; e < emax; e++) {
            m = fmaxf(m, xsh[e]);
            Sp[bo + (e - i)] = m;
        }
    }
    __syncthreads();

    // ---- write loop: two independent cursors, 512-chunk stride each.
    // Cursor A: chunks tid, tid+512, tid+1024. Cursor B: tid+256, tid+768.
    // (i,j) per cursor advance by 2048 elements = +31 rows, +33 cols.
    int iA, jA, iB, jB;
    { int er = tid << 2;          iA = er / 65; jA = er - iA * 65; }  // er < 1024
    { int er = (tid << 2) + 1024; iB = er / 65; jB = er - iB * 65; }  // er < 2048

    int qA = tid;
    int qB = tid + 256;

    #pragma unroll 1
    for (int s = 0; s < 2; s++) {
        emit_chunk<REL>(hid, msk, Sp, qA, iA, jA);
        emit_chunk<REL>(hid, msk, Sp, qB, iB, jB);
        qA += 512; iA += 31; jA += 33; if (jA >= NJ) { jA -= NJ; iA += 1; }
        qB += 512; iB += 31; jB += 33; if (jB >= NJ) { jB -= NJ; iB += 1; }
    }
    // tail: chunks 1024..1039 (cursor A, third step, tid < 16)
    if (tid < 16)
        emit_chunk<REL>(hid, msk, Sp, qA, iA, jA);
}

__global__ __launch_bounds__(256, 8)      // cap regs at 32: protect occupancy
void prop3d_kernel(const float* __restrict__ x, float* __restrict__ out,
                   long half_elems) {
    __shared__ float xsh[NC];
    __shared__ float Sp[4096];            // rel0 worst case: 64x64 (16 KB)

    const int bid = blockIdx.x;
    const int bd  = bid >> 2;             // b*512 + d
    const int rel = bid & 3;
    const int b   = bd >> 9;
    const int d   = bd & 511;
    const int tid = threadIdx.x;

    const float* xrow = x + ((((long)(b << 2) + rel) * D_DIM) + d) * NC;
    float* hid = out + (long)bd * REGION + rel * RELBLK;
    float* msk = hid + half_elems;

    switch (rel) {
        case 0:  prop3d_rel<0>(xrow, hid, msk, Sp, xsh, tid); break;
        case 1:  prop3d_rel<1>(xrow, hid, msk, Sp, xsh, tid); break;
        case 2:  prop3d_rel<2>(xrow, hid, msk, Sp, xsh, tid); break;
        default: prop3d_rel<3>(xrow, hid, msk, Sp, xsh, tid); break;
    }
}

extern "C" void kernel_launch(void* const* d_in, const int* in_sizes, int n_in,
                              void* d_out, int out_size) {
    const float* x = (const float*)d_in[0];
    float* out = (float*)d_out;
    long half = (long)out_size / 2;       // map_hidden elements; map_mask follows

    prop3d_kernel<<<B_DIM * D_DIM * 4, 256>>>(x, out, half);
}

// round 16
// speedup vs baseline: 1.1939x; 1.0370x over previous
#include <cuda_runtime.h>
#include <cstdint>

// x: (B=8, ns=4, D=512, nc=64) fp32
// out: concat(map_hidden, map_mask), each (B, D, 4, 64, 65) fp32.
// For rel in 0..3, base=1<<rel:
//   out[b,d,rel,i,j] = max(x[b,rel,d, i .. i+k-1]) where k=(j-i)/base,
//   valid when i%base==0, (j-i)%base==0, i<j<64. Mask = 1.0 at hits.
//
// Pure store-bound (~545 MB out). NEW drain path: each CTA composes its
// whole rel block (hidden + mask, 2 x 16640 B) in shared memory — the
// running-max sequence IS the row content, written directly at hit
// positions after a zero-fill — then drains with two 1D TMA bulk stores
// (cp.async.bulk.global.shared::cta). No per-chunk control math, no STG.

#define B_DIM 8
#define D_DIM 512
#define NC 64
#define NJ 65
#define REGION (4 * NC * NJ)        // 16640 floats per half per (b,d)
#define RELBLK (NC * NJ)            // 4160 floats per rel block
#define RELBYTES (RELBLK * 4)       // 16640 bytes

__device__ __forceinline__ uint32_t smem_u32(const void* p) {
    return (uint32_t)__cvta_generic_to_shared(p);
}

__global__ __launch_bounds__(256, 6)
void prop3d_kernel(const float* __restrict__ x, float* __restrict__ out,
                   long half_elems) {
    __shared__ __align__(16) float hidS[RELBLK];   // 16640 B
    __shared__ __align__(16) float mskS[RELBLK];   // 16640 B
    __shared__ float xsh[NC];

    const int bid = blockIdx.x;
    const int bd  = bid >> 2;             // b*512 + d
    const int rel = bid & 3;
    const int b   = bd >> 9;
    const int d   = bd & 511;
    const int tid = threadIdx.x;

    // ---- issue input load early ----
    float xv = 0.0f;
    if (tid < NC)
        xv = x[((((long)(b << 2) + rel) * D_DIM) + d) * NC + tid];

    // ---- zero-fill both SMEM images (4160 words each; 16B vector fill) ----
    {
        const float4 z4 = make_float4(0.0f, 0.0f, 0.0f, 0.0f);
        float4* h4 = reinterpret_cast<float4*>(hidS);
        float4* m4 = reinterpret_cast<float4*>(mskS);
        #pragma unroll
        for (int q = tid; q < RELBLK / 4; q += 256) {
            h4[q] = z4;
            m4[q] = z4;
        }
    }
    if (tid < NC) xsh[tid] = xv;
    __syncthreads();

    // ---- compose hits directly: row i = r<<rel, hits at j = i + k*base,
    // value = running max of xsh[i .. i+k-1], k = 1..kmax. ----
    const int W = NC >> rel;              // rows with i % base == 0
    if (tid < W) {
        const int i    = tid << rel;
        const int kmax = (NC - 1 - i) >> rel;
        const int rowb = i * NJ + i;      // position of j = i
        float m = xsh[i];
        #pragma unroll 4
        for (int k = 1; k <= kmax; k++) {
            // window is k elements: x[i .. i+k-1]
            if (k > 1) m = fmaxf(m, xsh[i + k - 1]);
            int off = rowb + (k << rel);
            hidS[off] = m;
            mskS[off] = 1.0f;
        }
    }
    __syncthreads();

    // ---- drain: two 1D TMA bulk stores, then wait before CTA exit ----
    if (tid == 0) {
        asm volatile("fence.proxy.async.shared::cta;" ::: "memory");
        float* hidG = out + (long)bd * REGION + rel * RELBLK;
        float* mskG = hidG + half_elems;
        uint32_t hs = smem_u32(hidS);
        uint32_t ms = smem_u32(mskS);
        asm volatile(
            "cp.async.bulk.global.shared::cta.bulk_group [%0], [%1], %2;"
            :: "l"(hidG), "r"(hs), "n"(RELBYTES) : "memory");
        asm volatile(
            "cp.async.bulk.global.shared::cta.bulk_group [%0], [%1], %2;"
            :: "l"(mskG), "r"(ms), "n"(RELBYTES) : "memory");
        asm volatile("cp.async.bulk.commit_group;" ::: "memory");
        asm volatile("cp.async.bulk.wait_group 0;" ::: "memory");
    }
    // __syncthreads not needed after: SMEM lifetime ends only when all
    // threads exit, and tid 0 holds the CTA until the bulk reads complete.
    __syncthreads();
}

extern "C" void kernel_launch(void* const* d_in, const int* in_sizes, int n_in,
                              void* d_out, int out_size) {
    const float* x = (const float*)d_in[0];
    float* out = (float*)d_out;
    long half = (long)out_size / 2;       // map_hidden elements; map_mask follows

    prop3d_kernel<<<B_DIM * D_DIM * 4, 256>>>(x, out, half);
}

// round 17
// speedup vs baseline: 1.2006x; 1.0056x over previous
#include <cuda_runtime.h>
#include <cstdint>

// x: (B=8, ns=4, D=512, nc=64) fp32
// out: concat(map_hidden, map_mask), each (B, D, 4, 64, 65) fp32.
// For rel in 0..3, base=1<<rel:
//   out[b,d,rel,i,j] = max(x[b,rel,d, i .. i+k-1]) where k=(j-i)/base,
//   valid when i%base==0, (j-i)%base==0, i<j<64. Mask = 1.0 at hits.
//
// Pure store-bound (~545 MB out). Compose-in-SMEM + TMA bulk-store drain.
// Grid = bd x rel x {hidden, mask} (32768 CTAs, 16.6 KB smem each ->
// thread-capped 8 CTAs/SM, full 64-warp occupancy). Mask CTAs need no
// input load. CTA slot released via wait_group.read as soon as TMA has
// consumed SMEM (write completion handled by the memory system).

#define B_DIM 8
#define D_DIM 512
#define NC 64
#define NJ 65
#define REGION (4 * NC * NJ)        // 16640 floats per half per (b,d)
#define RELBLK (NC * NJ)            // 4160 floats per rel block
#define RELBYTES (RELBLK * 4)       // 16640 bytes (multiple of 16)

__device__ __forceinline__ uint32_t smem_u32(const void* p) {
    return (uint32_t)__cvta_generic_to_shared(p);
}

__global__ __launch_bounds__(256, 8)
void prop3d_kernel(const float* __restrict__ x, float* __restrict__ out,
                   long half_elems) {
    __shared__ __align__(16) float blkS[RELBLK];   // 16640 B output image
    __shared__ float xsh[NC];

    const int bid  = blockIdx.x;
    const int rel  = bid & 3;
    const int hsel = (bid >> 2) & 1;     // 0 = hidden, 1 = mask
    const int bd   = bid >> 3;           // b*512 + d
    const int b    = bd >> 9;
    const int d    = bd & 511;
    const int tid  = threadIdx.x;

    // ---- hidden CTAs: issue input load early (mask CTAs skip it) ----
    float xv = 0.0f;
    if (hsel == 0 && tid < NC)
        xv = x[((((long)(b << 2) + rel) * D_DIM) + d) * NC + tid];

    // ---- zero-fill the SMEM image (4160 words, 16B vector fill) ----
    {
        const float4 z4 = make_float4(0.0f, 0.0f, 0.0f, 0.0f);
        float4* b4 = reinterpret_cast<float4*>(blkS);
        #pragma unroll
        for (int q = tid; q < RELBLK / 4; q += 256)
            b4[q] = z4;
    }
    if (hsel == 0 && tid < NC) xsh[tid] = xv;
    __syncthreads();

    // ---- compose hits: row i = r<<rel, hits at j = i + k*base,
    // k = 1..kmax. Hidden: running max of xsh[i..i+k-1]; mask: 1.0. ----
    const int W = NC >> rel;             // rows with i % base == 0
    if (tid < W) {
        const int i    = tid << rel;
        const int kmax = (NC - 1 - i) >> rel;
        const int rowb = i * NJ + i;     // position of j = i
        if (hsel == 0) {
            float m = xsh[i];
            #pragma unroll 4
            for (int k = 1; k <= kmax; k++) {
                if (k > 1) m = fmaxf(m, xsh[i + k - 1]);
                blkS[rowb + (k << rel)] = m;
            }
        } else {
            #pragma unroll 4
            for (int k = 1; k <= kmax; k++)
                blkS[rowb + (k << rel)] = 1.0f;
        }
    }
    __syncthreads();

    // ---- drain: one 1D TMA bulk store; release SMEM via read-wait ----
    if (tid == 0) {
        asm volatile("fence.proxy.async.shared::cta;" ::: "memory");
        float* dstG = out + (long)bd * REGION + rel * RELBLK
                    + (hsel ? half_elems : 0);
        uint32_t ss = smem_u32(blkS);
        asm volatile(
            "cp.async.bulk.global.shared::cta.bulk_group [%0], [%1], %2;"
            :: "l"(dstG), "r"(ss), "n"(RELBYTES) : "memory");
        asm volatile("cp.async.bulk.commit_group;" ::: "memory");
        asm volatile("cp.async.bulk.wait_group.read 0;" ::: "memory");
    }
    __syncthreads();
}

extern "C" void kernel_launch(void* const* d_in, const int* in_sizes, int n_in,
                              void* d_out, int out_size) {
    const float* x = (const float*)d_in[0];
    float* out = (float*)d_out;
    long half = (long)out_size / 2;      // map_hidden elements; map_mask follows

    prop3d_kernel<<<B_DIM * D_DIM * 4 * 2, 256>>>(x, out, half);
}